// round 7
// baseline (speedup 1.0000x reference)
#include <cuda_runtime.h>

// ---------------------------------------------------------------------------
// QWTForward: bicubic 2x downsample + 16 scaled copies.
//
//   D = downsample_bicubic(image)                 (4,16,256,256)
//   LL[b, g*16+c]        = D[b,c] * sLL[g]        (4,64,256,256)
//   H [b, g*16+c, band]  = D[b,c] * sH[band][g]   (4,64,3,256,256)
//
// R6: two-stage smem tile. Block = 4 output rows x 256 output cols.
//   Stage 1: load 10 input rows, horizontal conv -> smem h[10][64] float4.
//   Stage 2: vertical conv from smem (aligned LDS.128), 16 streaming stores.
// ---------------------------------------------------------------------------

#define B_    4
#define C_    16
#define HIN   512
#define WIN   512
#define HOUT  256
#define WOUT  256
#define PLANE (HOUT * WOUT)                // 65536
#define LL_TOTAL ((size_t)B_ * 64 * PLANE) // 16,777,216 floats

__global__ __launch_bounds__(256)
void qwt_kernel(const float* __restrict__ image,
                const float* __restrict__ gl,
                const float* __restrict__ gh,
                const float* __restrict__ fl,
                const float* __restrict__ fh,
                float* __restrict__ out) {
    __shared__ float4 hsm[10][64];   // horizontal-filtered rows
    __shared__ float sc[16];

    const int tid  = threadIdx.x;
    const int lane = tid & 31;

    // Warp 0: lanes 0-3 each serially sum one 16-tap filter IN INDEX ORDER
    // (sums cancel to ~1e-8; association order is semantically significant).
    if (tid < 32) {
        float s = 0.f;
        if (lane < 4) {
            const float* __restrict__ f =
                (lane == 0) ? gl : (lane == 1) ? gh : (lane == 2) ? fl : fh;
            #pragma unroll
            for (int i = 0; i < 16; i++) s += f[i];
        }
        float vg = __shfl_sync(0xffffffffu, s, 0);
        float vh = __shfl_sync(0xffffffffu, s, 1);
        float vl = __shfl_sync(0xffffffffu, s, 2);
        float vf = __shfl_sync(0xffffffffu, s, 3);
        if (lane < 16) {
            int t = lane;
            bool hiA = (t >= 8);
            bool hiB = (t >> 2) & 1;
            float first  = (t & 1)        ? (hiA ? vf : vl) : (hiA ? vh : vg);
            float second = ((t >> 1) & 1) ? (hiB ? vf : vl) : (hiB ? vh : vg);
            sc[t] = first * second;
        }
    }

    // Block decomposition: blockIdx.x = plane*64 + by  (y-adjacent blocks
    // consecutive -> halo rows stay hot in L2).
    const int by    = blockIdx.x & 63;       // output row group (4 rows)
    const int plane = blockIdx.x >> 6;       // b*16 + c
    const int Y0    = by * 4;

    const float w0 = -0.09375f, w1 = 0.59375f, w2 = 0.59375f, w3 = -0.09375f;

    const float* __restrict__ src = image + (size_t)plane * (HIN * WIN);

    // ---- Stage 1: horizontal conv of 10 input rows into smem ----
    {
        const int x4 = tid & 63;          // float4-pair column within row
        const int rs = tid >> 6;          // 0..3 (constant within a warp)
        const int base = 8 * x4;
        const bool left_clamp  = (x4 == 0);
        const bool left_shfl   = (!left_clamp) && (lane > 0);
        const bool right_clamp = (x4 == 63);
        const bool right_shfl  = (!right_clamp) && (lane < 31);

        #pragma unroll
        for (int k = 0; k < 3; k++) {
            int r = k * 4 + rs;           // uniform per warp
            if (r < 10) {
                int ry = min(max(2 * Y0 - 1 + r, 0), HIN - 1);
                const float* __restrict__ row = src + (size_t)ry * WIN;
                const float4* __restrict__ row4 = reinterpret_cast<const float4*>(row);
                float4 bv = __ldg(row4 + 2 * x4);       // cols base..base+3
                float4 cv = __ldg(row4 + 2 * x4 + 1);   // cols base+4..base+7

                float up = __shfl_up_sync(0xffffffffu, cv.w, 1);
                float dn = __shfl_down_sync(0xffffffffu, bv.x, 1);
                float vm1 = left_clamp  ? bv.x : (left_shfl  ? up : __ldg(row + base - 1));
                float vp8 = right_clamp ? cv.w : (right_shfl ? dn : __ldg(row + base + 8));

                float4 h;
                h.x = w0 * vm1  + w1 * bv.x + w2 * bv.y + w3 * bv.z;
                h.y = w0 * bv.y + w1 * bv.z + w2 * bv.w + w3 * cv.x;
                h.z = w0 * bv.w + w1 * cv.x + w2 * cv.y + w3 * cv.z;
                h.w = w0 * cv.y + w1 * cv.z + w2 * cv.w + w3 * vp8;
                hsm[r][x4] = h;
            }
        }
    }
    __syncthreads();

    // ---- Stage 2: vertical conv + 16 scaled streaming stores ----
    {
        const int x4 = tid & 63;
        const int j  = tid >> 6;          // 0..3 output row within block
        const int y  = Y0 + j;

        // output y uses input rows 2y-1..2y+2 = h rows 2j..2j+3
        float4 h0 = hsm[2 * j + 0][x4];
        float4 h1 = hsm[2 * j + 1][x4];
        float4 h2 = hsm[2 * j + 2][x4];
        float4 h3 = hsm[2 * j + 3][x4];

        float d0 = w0 * h0.x + w1 * h1.x + w2 * h2.x + w3 * h3.x;
        float d1 = w0 * h0.y + w1 * h1.y + w2 * h2.y + w3 * h3.y;
        float d2 = w0 * h0.z + w1 * h1.z + w2 * h2.z + w3 * h3.z;
        float d3 = w0 * h0.w + w1 * h1.w + w2 * h2.w + w3 * h3.w;

        size_t p = (size_t)y * WOUT + (size_t)x4 * 4;

        #pragma unroll
        for (int g = 0; g < 4; g++) {
            size_t ch = (size_t)plane % 16;  // c
            // plane = b*16 + c
            int bb = plane >> 4;
            size_t chan = (size_t)(bb * 64 + g * 16 + (plane & 15));
            {
                float s = sc[g];
                __stcs(reinterpret_cast<float4*>(out + chan * PLANE + p),
                       make_float4(d0 * s, d1 * s, d2 * s, d3 * s));
            }
            #pragma unroll
            for (int band = 0; band < 3; band++) {
                float s = sc[4 + band * 4 + g];
                __stcs(reinterpret_cast<float4*>(out + LL_TOTAL + (chan * 3 + band) * PLANE + p),
                       make_float4(d0 * s, d1 * s, d2 * s, d3 * s));
            }
            (void)ch;
        }
    }
}

extern "C" void kernel_launch(void* const* d_in, const int* in_sizes, int n_in,
                              void* d_out, int out_size) {
    const float* image = (const float*)d_in[0];
    const float* gl    = (const float*)d_in[1];
    const float* gh    = (const float*)d_in[2];
    const float* fl    = (const float*)d_in[3];
    const float* fh    = (const float*)d_in[4];
    float* out = (float*)d_out;

    // blocks = (B*C) * (HOUT/4) = 64 * 64 = 4096, 256 threads each
    qwt_kernel<<<4096, 256>>>(image, gl, gh, fl, fh, out);
}